// round 1
// baseline (speedup 1.0000x reference)
#include <cuda_runtime.h>
#include <math.h>

#define HID   256
#define NSTY  8
#define SDIM  64
#define MT    64          // pixels per CTA tile
#define KT    16          // k-tile rows
#define APITCH 68         // act row stride in floats (272B, 16B-aligned, bank-staggered)

// dynamic smem partition sizes (floats)
#define SM_ACT   (HID * APITCH)      // 17408
#define SM_WBUF  (KT * HID)          // 4096
#define SM_RGB   (3 * MT)            // 192
#define SM_W0    (3 * HID)           // 768
#define SM_C0    (HID)               // 256
#define SMEM_FLOATS (SM_ACT + SM_WBUF + SM_RGB + SM_W0 + SM_C0)
#define SMEM_BYTES  (SMEM_FLOATS * 4)   // 90,880 B

// per-style folded bias: c0[s][j] = b0[j] + sum_d emb[s][d] * W0[3+d][j]
__device__ float g_c0[NSTY][HID];

__global__ void c0_kernel(const float* __restrict__ emb,
                          const float* __restrict__ W0,
                          const float* __restrict__ b0) {
    int s = blockIdx.x, j = threadIdx.x;
    float a = b0[j];
    const float* e = emb + s * SDIM;
    #pragma unroll 8
    for (int d = 0; d < SDIM; d++)
        a += e[d] * W0[(3 + d) * HID + j];
    g_c0[s][j] = a;
}

__device__ __forceinline__ float gelu_f(float x) {
    return 0.5f * x * (1.0f + erff(x * 0.70710678118654752f));
}

__global__ __launch_bounds__(256, 2)
void nilut_main(const float* __restrict__ rgb, const int* __restrict__ sidx,
                const float* __restrict__ W0,
                const float* __restrict__ W1, const float* __restrict__ b1,
                const float* __restrict__ W2, const float* __restrict__ b2,
                const float* __restrict__ W3, const float* __restrict__ b3,
                float* __restrict__ out, int HW)
{
    extern __shared__ float sm[];
    float* act  = sm;                      // [HID][APITCH]  act[k*APITCH + m]
    float* wbuf = act  + SM_ACT;           // [KT][HID]
    float* rgbs = wbuf + SM_WBUF;          // [3][MT]
    float* w0s  = rgbs + SM_RGB;           // [3][HID]
    float* c0s  = w0s  + SM_W0;            // [HID]

    const int tid = threadIdx.x;
    const int mg  = tid & 7;               // m-group (8 groups of 8 pixels)
    const int ng  = tid >> 3;              // n-group (32 groups of 8 outputs)
    const int m0  = mg * 8, n0 = ng * 8;

    const long long p0  = (long long)blockIdx.x * MT;
    const int b   = (int)(p0 / HW);        // whole tile inside one image (HW % MT == 0)
    const int hw0 = (int)(p0 % HW);
    const int style = sidx[b];

    // stage rgb tile, W0 rgb-rows, folded style bias
    for (int i = tid; i < 3 * MT; i += 256) {
        int c = i / MT, m = i % MT;
        rgbs[c * MT + m] = rgb[((long long)b * 3 + c) * HW + hw0 + m];
    }
    for (int i = tid; i < 3 * HID; i += 256) w0s[i] = W0[i];
    c0s[tid] = g_c0[style][tid];
    __syncthreads();

    float acc[8][8];

    // ---- layer 0: h = gelu(rgb @ W0[0:3] + c0[style]) ----
    {
        float r0[8], r1[8], r2[8];
        #pragma unroll
        for (int i = 0; i < 8; i++) {
            r0[i] = rgbs[0 * MT + m0 + i];
            r1[i] = rgbs[1 * MT + m0 + i];
            r2[i] = rgbs[2 * MT + m0 + i];
        }
        #pragma unroll
        for (int j = 0; j < 8; j++) {
            float w00 = w0s[n0 + j], w01 = w0s[HID + n0 + j], w02 = w0s[2 * HID + n0 + j];
            float c = c0s[n0 + j];
            #pragma unroll
            for (int i = 0; i < 8; i++)
                acc[i][j] = c + r0[i] * w00 + r1[i] * w01 + r2[i] * w02;
        }
        #pragma unroll
        for (int j = 0; j < 8; j++)
            #pragma unroll
            for (int i = 0; i < 8; i++)
                act[(n0 + j) * APITCH + m0 + i] = gelu_f(acc[i][j]);
    }
    __syncthreads();

    // ---- hidden layers 1 & 2: act = gelu(act @ W + b), 256x256 GEMM per tile ----
    const float* Ws[2] = {W1, W2};
    const float* bs[2] = {b1, b2};
    for (int layer = 0; layer < 2; layer++) {
        const float* __restrict__ Wg = Ws[layer];
        const float* __restrict__ bg = bs[layer];
        #pragma unroll
        for (int j = 0; j < 8; j++) {
            float bv = __ldg(&bg[n0 + j]);
            #pragma unroll
            for (int i = 0; i < 8; i++) acc[i][j] = bv;
        }
        for (int kt = 0; kt < HID / KT; kt++) {
            // cooperative load of W k-tile [KT][HID] (4096 floats = 1024 float4)
            const float4* src = reinterpret_cast<const float4*>(Wg + kt * KT * HID);
            float4* dst = reinterpret_cast<float4*>(wbuf);
            #pragma unroll
            for (int r = 0; r < 4; r++)
                dst[tid + r * 256] = src[tid + r * 256];
            __syncthreads();
            #pragma unroll
            for (int k = 0; k < KT; k++) {
                const float4* ar = reinterpret_cast<const float4*>(act + (kt * KT + k) * APITCH + m0);
                float4 a0 = ar[0], a1 = ar[1];
                const float4* wr = reinterpret_cast<const float4*>(wbuf + k * HID + n0);
                float4 wv0 = wr[0], wv1 = wr[1];
                float a[8] = {a0.x, a0.y, a0.z, a0.w, a1.x, a1.y, a1.z, a1.w};
                float w[8] = {wv0.x, wv0.y, wv0.z, wv0.w, wv1.x, wv1.y, wv1.z, wv1.w};
                #pragma unroll
                for (int j = 0; j < 8; j++)
                    #pragma unroll
                    for (int i = 0; i < 8; i++)
                        acc[i][j] += a[i] * w[j];
            }
            __syncthreads();   // also guarantees all act reads done before epilogue writes
        }
        #pragma unroll
        for (int j = 0; j < 8; j++)
            #pragma unroll
            for (int i = 0; i < 8; i++)
                act[(n0 + j) * APITCH + m0 + i] = gelu_f(acc[i][j]);
        __syncthreads();
    }

    // ---- output layer: out = sigmoid(act @ W3 + b3), W3 is [HID][3] ----
    for (int i = tid; i < HID * 3; i += 256) wbuf[i] = W3[i];   // reuse wbuf
    __syncthreads();
    if (tid < 3 * MT) {
        int m = tid % MT;
        int c = tid / MT;
        float a = __ldg(&b3[c]);
        #pragma unroll 8
        for (int k = 0; k < HID; k++)
            a += act[k * APITCH + m] * wbuf[k * 3 + c];
        out[((long long)b * 3 + c) * HW + hw0 + m] = 1.0f / (1.0f + expf(-a));
    }
}

extern "C" void kernel_launch(void* const* d_in, const int* in_sizes, int n_in,
                              void* d_out, int out_size) {
    const float* rgb = (const float*)d_in[0];
    const int*   sidx = (const int*)d_in[1];
    const float* emb = (const float*)d_in[2];
    const float* W0  = (const float*)d_in[3];
    const float* b0  = (const float*)d_in[4];
    const float* W1  = (const float*)d_in[5];
    const float* b1  = (const float*)d_in[6];
    const float* W2  = (const float*)d_in[7];
    const float* b2  = (const float*)d_in[8];
    const float* W3  = (const float*)d_in[9];
    const float* b3  = (const float*)d_in[10];
    float* out = (float*)d_out;

    const int B = in_sizes[1];
    const long long HW = (long long)in_sizes[0] / (3LL * B);
    const long long N  = (long long)B * HW;

    cudaFuncSetAttribute(nilut_main, cudaFuncAttributeMaxDynamicSharedMemorySize, SMEM_BYTES);

    c0_kernel<<<NSTY, HID>>>(emb, W0, b0);
    nilut_main<<<(unsigned)(N / MT), 256, SMEM_BYTES>>>(
        rgb, sidx, W0, W1, b1, W2, b2, W3, b3, out, (int)HW);
}

// round 6
// speedup vs baseline: 2.1622x; 2.1622x over previous
#include <cuda_runtime.h>
#include <cuda_bf16.h>
#include <math.h>
#include <stdint.h>

#define HID 256
#define NSTY 8
#define SDIM 64
#define MT 128
#define THREADS 256

// activation SMEM pitch: 264 bf16 = 528B (33*16B -> conflict-free ldmatrix rows)
#define APITCHB 528

// SMEM layout (bytes)
#define SO_ACTHI 0
#define SO_ACTLO 67584            // 128*528
#define SO_WBUF  135168           // 2 x 32KB double buffer
#define SO_W0    200704           // 3*256 f32
#define SO_C0    203776           // 256 f32
#define SO_B1    204800           // 256 f32
#define SO_B2    205824           // 256 f32
#define SO_W3    206848           // 3*256 f32 (w3s[c*256+k])
#define SO_B3    209920           // 3 f32 (+pad)
#define SO_PBUF  209936           // 3*128 f32
#define SMEM_TOTAL 211488

// ---------------- device globals ----------------
__device__ float g_c0[NSTY][HID];
// [layer][term(hi/lo)] x 65536 bf16 (256x256), laid out as [kc(16)][nb(32)][sub(2)][row(8)][col(8)]
__device__ __align__(16) __nv_bfloat16 g_Wm[2][2][65536];

// ---------------- helpers ----------------
__device__ __forceinline__ uint32_t smem_to_u32(const void* p) {
    uint32_t a;
    asm("{ .reg .u64 t; cvta.to.shared.u64 t, %1; cvt.u32.u64 %0, t; }" : "=r"(a) : "l"(p));
    return a;
}
#define LDSM4(R, addr) \
    asm volatile("ldmatrix.sync.aligned.m8n8.x4.shared.b16 {%0,%1,%2,%3}, [%4];" \
        : "=r"((R)[0]), "=r"((R)[1]), "=r"((R)[2]), "=r"((R)[3]) : "r"(addr))
#define MMA_B16(dd, a, b0_, b1_) \
    asm volatile("mma.sync.aligned.m16n8k16.row.col.f32.bf16.bf16.f32 " \
        "{%0,%1,%2,%3}, {%4,%5,%6,%7}, {%8,%9}, {%0,%1,%2,%3};" \
        : "+f"((dd)[0]), "+f"((dd)[1]), "+f"((dd)[2]), "+f"((dd)[3]) \
        : "r"((a)[0]), "r"((a)[1]), "r"((a)[2]), "r"((a)[3]), "r"(b0_), "r"(b1_))
#define CP_ASYNC16(dst, src) \
    asm volatile("cp.async.cg.shared.global [%0], [%1], 16;" :: "r"(dst), "l"(src) : "memory")
#define CP_COMMIT() asm volatile("cp.async.commit_group;" ::: "memory")
#define CP_WAIT1()  asm volatile("cp.async.wait_group 1;" ::: "memory")
#define CP_WAIT0()  asm volatile("cp.async.wait_group 0;" ::: "memory")

__device__ __forceinline__ float gelu_f(float x) {
    // 0.5*x*(1+erf(x/sqrt(2))), erf via Abramowitz-Stegun 7.1.26 (|err|<=1.5e-7)
    float u  = x * 0.70710678118654752f;
    float au = fabsf(u);
    float t  = __fdividef(1.0f, fmaf(0.3275911f, au, 1.0f));
    float p  = t * fmaf(t, fmaf(t, fmaf(t, fmaf(t, 1.061405429f, -1.453152027f),
                                        1.421413741f), -0.284496736f), 0.254829592f);
    float er = 1.0f - p * __expf(-au * au);
    er = copysignf(er, u);
    return 0.5f * x * (1.0f + er);
}
__device__ __forceinline__ uint32_t pack2(float a, float b) {
    __nv_bfloat162 t = __floats2bfloat162_rn(a, b);
    return *reinterpret_cast<uint32_t*>(&t);
}

// ---------------- prologue kernels ----------------
__global__ void c0_kernel(const float* __restrict__ emb,
                          const float* __restrict__ W0,
                          const float* __restrict__ b0) {
    int s = blockIdx.x, j = threadIdx.x;
    float a = b0[j];
    const float* e = emb + s * SDIM;
    #pragma unroll 8
    for (int d = 0; d < SDIM; d++) a += e[d] * W0[(3 + d) * HID + j];
    g_c0[s][j] = a;
}

__global__ void wsplit_kernel(const float* __restrict__ W1, const float* __restrict__ W2) {
    int l = blockIdx.x >> 8, n = blockIdx.x & 255, k = threadIdx.x;
    const float* Ws = l ? W2 : W1;
    float w = Ws[k * HID + n];
    __nv_bfloat16 h = __float2bfloat16(w);
    float lo = w - __bfloat162float(h);
    int off = ((((k >> 4) * 32 + (n >> 3)) * 2 + ((k >> 3) & 1)) * 8 + (n & 7)) * 8 + (k & 7);
    g_Wm[l][0][off] = h;
    g_Wm[l][1][off] = __float2bfloat16(lo);
}

// ---------------- weight chunk streaming ----------------
__device__ __forceinline__ void load_chunk(int g, uint32_t sb, int tid) {
    int l = g >> 3, kc2 = g & 7, bsel = g & 1;
    uint32_t dbase = sb + SO_WBUF + (uint32_t)bsel * 32768u;
    #pragma unroll
    for (int i = 0; i < 8; i++) {
        int idx = tid + i * 256;               // 0..2047 (16B units)
        int term = idx >> 10;                  // 16KB per term
        int r = idx & 1023;
        const char* src = (const char*)&g_Wm[l][term][0] + kc2 * 16384 + r * 16;
        uint32_t dst = dbase + (uint32_t)term * 16384u + (uint32_t)r * 16u;
        CP_ASYNC16(dst, src);
    }
    CP_COMMIT();
}

// ---------------- main kernel ----------------
__global__ void __launch_bounds__(THREADS, 1)
nilut_mma(const float* __restrict__ rgb, const int* __restrict__ sidx,
          const float* __restrict__ W0,
          const float* __restrict__ b1, const float* __restrict__ b2,
          const float* __restrict__ W3, const float* __restrict__ b3,
          float* __restrict__ out, int HW)
{
    extern __shared__ __align__(128) char smem[];
    uint32_t sb = smem_to_u32(smem);
    float* w0s  = (float*)(smem + SO_W0);
    float* c0s  = (float*)(smem + SO_C0);
    float* b1s  = (float*)(smem + SO_B1);
    float* b2s  = (float*)(smem + SO_B2);
    float* w3s  = (float*)(smem + SO_W3);
    float* b3s  = (float*)(smem + SO_B3);
    float* pbuf = (float*)(smem + SO_PBUF);

    const int tid = threadIdx.x, wid = tid >> 5, lane = tid & 31;
    const int warp_m = wid >> 2, warp_n = wid & 3;

    const long long base = (long long)blockIdx.x * MT;
    const int b = (int)(base / HW), hw0 = (int)(base % HW);
    const int style = sidx[b];

    // prefetch first two weight chunks (layer-1 weights)
    load_chunk(0, sb, tid);
    load_chunk(1, sb, tid);

    // stage small tensors
    for (int i = tid; i < 768; i += THREADS) w0s[i] = W0[i];
    c0s[tid] = g_c0[style][tid];
    b1s[tid] = b1[tid];
    b2s[tid] = b2[tid];
    for (int i = tid; i < 768; i += THREADS) { int c = i >> 8, k = i & 255; w3s[i] = W3[k * 3 + c]; }
    if (tid < 3) b3s[tid] = b3[tid];
    if (tid < 128) { pbuf[tid] = 0.f; pbuf[128 + tid] = 0.f; pbuf[256 + tid] = 0.f; }
    __syncthreads();

    // ---- layer 0: SIMT, write act hi/lo ----
    {
        const int m = tid >> 1, h = tid & 1;
        const float r0 = rgb[((long long)b * 3 + 0) * HW + hw0 + m];
        const float r1 = rgb[((long long)b * 3 + 1) * HW + hw0 + m];
        const float r2 = rgb[((long long)b * 3 + 2) * HW + hw0 + m];
        uint32_t arow = sb + SO_ACTHI + (uint32_t)m * APITCHB + (uint32_t)h * 256u;
        #pragma unroll 4
        for (int i = 0; i < 64; i++) {
            int n = h * 128 + 2 * i;
            float z0 = c0s[n]     + r0 * w0s[n]     + r1 * w0s[256 + n]     + r2 * w0s[512 + n];
            float z1 = c0s[n + 1] + r0 * w0s[n + 1] + r1 * w0s[256 + n + 1] + r2 * w0s[512 + n + 1];
            float g0 = gelu_f(z0), g1 = gelu_f(z1);
            uint32_t hi = pack2(g0, g1);
            __nv_bfloat162 hv = *reinterpret_cast<__nv_bfloat162*>(&hi);
            uint32_t lo = pack2(g0 - __bfloat162float(hv.x), g1 - __bfloat162float(hv.y));
            *(uint32_t*)(smem + (arow - sb) + 4u * i) = hi;
            *(uint32_t*)(smem + (arow - sb) + (SO_ACTLO - SO_ACTHI) + 4u * i) = lo;
        }
    }

    // per-lane ldmatrix offsets
    const uint32_t arow_l = (uint32_t)((lane & 7) + ((lane >> 3) & 1) * 8);
    const uint32_t akoff  = (uint32_t)(((lane >> 4) & 1) * 8);

    float d[4][8][4];
    #pragma unroll
    for (int mf = 0; mf < 4; mf++)
        #pragma unroll
        for (int nb = 0; nb < 8; nb++)
            #pragma unroll
            for (int e = 0; e < 4; e++) d[mf][nb][e] = 0.f;

    // ---- layers 1 & 2: 16 k32-chunks total ----
    for (int g = 0; g < 16; g++) {
        if (g == 15) { CP_WAIT0(); } else { CP_WAIT1(); }
        __syncthreads();
        const int bsel = g & 1;
        #pragma unroll
        for (int kcs = 0; kcs < 2; kcs++) {
            const int kc = (g & 7) * 2 + kcs;
            uint32_t ah[4][4], al[4][4];
            #pragma unroll
            for (int mf = 0; mf < 4; mf++) {
                uint32_t row = (uint32_t)(warp_m * 64 + mf * 16) + arow_l;
                uint32_t col = (uint32_t)(kc * 16) + akoff;
                uint32_t ad = sb + SO_ACTHI + row * APITCHB + col * 2u;
                LDSM4(ah[mf], ad);
                LDSM4(al[mf], ad + (SO_ACTLO - SO_ACTHI));
            }
            uint32_t wch = sb + SO_WBUF + (uint32_t)bsel * 32768u + (uint32_t)kcs * 8192u;
            #pragma unroll
            for (int nbp = 0; nbp < 4; nbp++) {
                uint32_t bd = wch + (uint32_t)((warp_n * 8 + nbp * 2) * 256) + (uint32_t)lane * 16u;
                uint32_t bh[4], bl[4];
                LDSM4(bh, bd);
                LDSM4(bl, bd + 16384u);
                #pragma unroll
                for (int h = 0; h < 2; h++) {
                    #pragma unroll
                    for (int mf = 0; mf < 4; mf++) {
                        float* dd = d[mf][nbp * 2 + h];
                        MMA_B16(dd, ah[mf], bh[2 * h], bh[2 * h + 1]);
                        MMA_B16(dd, al[mf], bh[2 * h], bh[2 * h + 1]);
                        MMA_B16(dd, ah[mf], bl[2 * h], bl[2 * h + 1]);
                    }
                }
            }
        }
        __syncthreads();
        if (g + 2 < 16) load_chunk(g + 2, sb, tid);

        if (g == 7) {
            // ---- mid epilogue: bias + GELU + split, write act hi/lo ----
            #pragma unroll
            for (int mf = 0; mf < 4; mf++) {
                #pragma unroll
                for (int nb = 0; nb < 8; nb++) {
                    int n0 = warp_n * 64 + nb * 8 + (lane & 3) * 2;
                    float bb0 = b1s[n0], bb1 = b1s[n0 + 1];
                    int mlow = warp_m * 64 + mf * 16 + (lane >> 2);
                    float g0 = gelu_f(d[mf][nb][0] + bb0);
                    float g1 = gelu_f(d[mf][nb][1] + bb1);
                    float g2 = gelu_f(d[mf][nb][2] + bb0);
                    float g3 = gelu_f(d[mf][nb][3] + bb1);
                    uint32_t hiA = pack2(g0, g1);
                    __nv_bfloat162 hA = *reinterpret_cast<__nv_bfloat162*>(&hiA);
                    uint32_t loA = pack2(g0 - __bfloat162float(hA.x), g1 - __bfloat162float(hA.y));
                    uint32_t hiB = pack2(g2, g3);
                    __nv_bfloat162 hB = *reinterpret_cast<__nv_bfloat162*>(&hiB);
                    uint32_t loB = pack2(g2 - __bfloat162float(hB.x), g3 - __bfloat162float(hB.y));
                    uint32_t offA = (uint32_t)mlow * APITCHB + (uint32_t)n0 * 2u;
                    uint32_t offB = offA + 8u * APITCHB;
                    *(uint32_t*)(smem + SO_ACTHI + offA) = hiA;
                    *(uint32_t*)(smem + SO_ACTLO + offA) = loA;
                    *(uint32_t*)(smem + SO_ACTHI + offB) = hiB;
                    *(uint32_t*)(smem + SO_ACTLO + offB) = loB;
                }
            }
            #pragma unroll
            for (int mf = 0; mf < 4; mf++)
                #pragma unroll
                for (int nb = 0; nb < 8; nb++)
                    #pragma unroll
                    for (int e = 0; e < 4; e++) d[mf][nb][e] = 0.f;
            // next iteration's leading __syncthreads orders these writes vs reads
        }
    }

    // ---- final epilogue: bias + GELU + layer3 dot + reduce ----
    #pragma unroll
    for (int mf = 0; mf < 4; mf++) {
        float pl0 = 0.f, pl1 = 0.f, pl2 = 0.f, ph0 = 0.f, ph1 = 0.f, ph2 = 0.f;
        #pragma unroll
        for (int nb = 0; nb < 8; nb++) {
            int n0 = warp_n * 64 + nb * 8 + (lane & 3) * 2;
            float bb0 = b2s[n0], bb1 = b2s[n0 + 1];
            float g0 = gelu_f(d[mf][nb][0] + bb0);
            float g1 = gelu_f(d[mf][nb][1] + bb1);
            float g2 = gelu_f(d[mf][nb][2] + bb0);
            float g3 = gelu_f(d[mf][nb][3] + bb1);
            float wa0 = w3s[n0], wa1 = w3s[n0 + 1];
            float wb0 = w3s[256 + n0], wb1 = w3s[256 + n0 + 1];
            float wc0 = w3s[512 + n0], wc1 = w3s[512 + n0 + 1];
            pl0 += g0 * wa0 + g1 * wa1;  ph0 += g2 * wa0 + g3 * wa1;
            pl1 += g0 * wb0 + g1 * wb1;  ph1 += g2 * wb0 + g3 * wb1;
            pl2 += g0 * wc0 + g1 * wc1;  ph2 += g2 * wc0 + g3 * wc1;
        }
        #pragma unroll
        for (int s = 1; s <= 2; s <<= 1) {
            pl0 += __shfl_xor_sync(0xFFFFFFFF, pl0, s);
            pl1 += __shfl_xor_sync(0xFFFFFFFF, pl1, s);
            pl2 += __shfl_xor_sync(0xFFFFFFFF, pl2, s);
            ph0 += __shfl_xor_sync(0xFFFFFFFF, ph0, s);
            ph1 += __shfl_xor_sync(0xFFFFFFFF, ph1, s);
            ph2 += __shfl_xor_sync(0xFFFFFFFF, ph2, s);
        }
        if ((lane & 3) == 0) {
            int mlow = warp_m * 64 + mf * 16 + (lane >> 2);
            atomicAdd(&pbuf[mlow], pl0);
            atomicAdd(&pbuf[128 + mlow], pl1);
            atomicAdd(&pbuf[256 + mlow], pl2);
            atomicAdd(&pbuf[mlow + 8], ph0);
            atomicAdd(&pbuf[128 + mlow + 8], ph1);
            atomicAdd(&pbuf[256 + mlow + 8], ph2);
        }
    }
    __syncthreads();
    if (tid < 128) {
        const int m = tid;
        #pragma unroll
        for (int c = 0; c < 3; c++) {
            float z = pbuf[c * 128 + m] + b3s[c];
            out[((long long)b * 3 + c) * HW + hw0 + m] = __fdividef(1.0f, 1.0f + __expf(-z));
        }
    }
}

// ---------------- launch ----------------
extern "C" void kernel_launch(void* const* d_in, const int* in_sizes, int n_in,
                              void* d_out, int out_size) {
    const float* rgb  = (const float*)d_in[0];
    const int*   sidx = (const int*)d_in[1];
    const float* emb  = (const float*)d_in[2];
    const float* W0   = (const float*)d_in[3];
    const float* b0   = (const float*)d_in[4];
    const float* W1   = (const float*)d_in[5];
    const float* b1   = (const float*)d_in[6];
    const float* W2   = (const float*)d_in[7];
    const float* b2   = (const float*)d_in[8];
    const float* W3   = (const float*)d_in[9];
    const float* b3   = (const float*)d_in[10];
    float* out = (float*)d_out;

    const int B = in_sizes[1];
    const long long HW = (long long)in_sizes[0] / (3LL * B);
    const long long N  = (long long)B * HW;

    static bool attr_set = false;
    if (!attr_set) {
        cudaFuncSetAttribute(nilut_mma, cudaFuncAttributeMaxDynamicSharedMemorySize, SMEM_TOTAL);
        attr_set = true;
    }

    c0_kernel<<<NSTY, HID>>>(emb, W0, b0);
    wsplit_kernel<<<512, HID>>>(W1, W2);
    nilut_mma<<<(unsigned)(N / MT), THREADS, SMEM_TOTAL>>>(
        rgb, sidx, W0, b1, b2, W3, b3, out, (int)HW);
}

// round 7
// speedup vs baseline: 2.5787x; 1.1926x over previous
#include <cuda_runtime.h>
#include <cuda_bf16.h>
#include <math.h>
#include <stdint.h>

#define HID 256
#define NSTY 8
#define SDIM 64
#define MT 64
#define THREADS 256

// activation SMEM pitch: 264 bf16 = 528B (conflict-staggered ldmatrix rows)
#define APITCHB 528

// SMEM layout (bytes)
#define SO_ACTHI 0                // 64*528 = 33792
#define SO_ACTLO 33792            // 33792
#define SO_WBUF  67584            // 2 x 16KB k16-chunk double buffer
#define SO_W0    100352           // 3*256 f32
#define SO_C0    103424           // 256 f32
#define SO_B1    104448           // 256 f32
#define SO_B2    105472           // 256 f32
#define SO_W3    106496           // 3*256 f32 (w3s[c*256+k])
#define SO_B3    109568           // 3 f32 (+pad)
#define SO_PBUF  109584           // 3*64 f32
#define SMEM_TOTAL 110352         // <= 113.5KB -> 2 CTAs/SM

// ---------------- device globals ----------------
__device__ float g_c0[NSTY][HID];
// [layer][term(hi/lo)] x 65536 bf16 (256x256), laid out as [kc(16)][nb(32)][sub(2)][row(8)][col(8)]
__device__ __align__(16) __nv_bfloat16 g_Wm[2][2][65536];

// ---------------- helpers ----------------
__device__ __forceinline__ uint32_t smem_to_u32(const void* p) {
    uint32_t a;
    asm("{ .reg .u64 t; cvta.to.shared.u64 t, %1; cvt.u32.u64 %0, t; }" : "=r"(a) : "l"(p));
    return a;
}
#define LDSM4(R, addr) \
    asm volatile("ldmatrix.sync.aligned.m8n8.x4.shared.b16 {%0,%1,%2,%3}, [%4];" \
        : "=r"((R)[0]), "=r"((R)[1]), "=r"((R)[2]), "=r"((R)[3]) : "r"(addr))
#define MMA_B16(dd, a, b0_, b1_) \
    asm volatile("mma.sync.aligned.m16n8k16.row.col.f32.bf16.bf16.f32 " \
        "{%0,%1,%2,%3}, {%4,%5,%6,%7}, {%8,%9}, {%0,%1,%2,%3};" \
        : "+f"((dd)[0]), "+f"((dd)[1]), "+f"((dd)[2]), "+f"((dd)[3]) \
        : "r"((a)[0]), "r"((a)[1]), "r"((a)[2]), "r"((a)[3]), "r"(b0_), "r"(b1_))
#define CP_ASYNC16(dst, src) \
    asm volatile("cp.async.cg.shared.global [%0], [%1], 16;" :: "r"(dst), "l"(src) : "memory")
#define CP_COMMIT() asm volatile("cp.async.commit_group;" ::: "memory")
#define CP_WAIT1()  asm volatile("cp.async.wait_group 1;" ::: "memory")
#define CP_WAIT0()  asm volatile("cp.async.wait_group 0;" ::: "memory")

__device__ __forceinline__ float gelu_f(float x) {
    // 0.5*x*(1+erf(x/sqrt(2))), erf via Abramowitz-Stegun 7.1.26 (|err|<=1.5e-7)
    float u  = x * 0.70710678118654752f;
    float au = fabsf(u);
    float t  = __fdividef(1.0f, fmaf(0.3275911f, au, 1.0f));
    float p  = t * fmaf(t, fmaf(t, fmaf(t, fmaf(t, 1.061405429f, -1.453152027f),
                                        1.421413741f), -0.284496736f), 0.254829592f);
    float er = 1.0f - p * __expf(-au * au);
    er = copysignf(er, u);
    return 0.5f * x * (1.0f + er);
}
__device__ __forceinline__ uint32_t pack2(float a, float b) {
    __nv_bfloat162 t = __floats2bfloat162_rn(a, b);
    return *reinterpret_cast<uint32_t*>(&t);
}

// ---------------- merged prologue kernel ----------------
__global__ void prep_kernel(const float* __restrict__ emb,
                            const float* __restrict__ W0,
                            const float* __restrict__ b0,
                            const float* __restrict__ W1,
                            const float* __restrict__ W2) {
    // weight split + rearrange (all 512 blocks)
    int l = blockIdx.x >> 8, n = blockIdx.x & 255, k = threadIdx.x;
    const float* Ws = l ? W2 : W1;
    float w = Ws[k * HID + n];
    __nv_bfloat16 h = __float2bfloat16(w);
    float lo = w - __bfloat162float(h);
    int off = ((((k >> 4) * 32 + (n >> 3)) * 2 + ((k >> 3) & 1)) * 8 + (n & 7)) * 8 + (k & 7);
    g_Wm[l][0][off] = h;
    g_Wm[l][1][off] = __float2bfloat16(lo);

    // folded per-style bias (blocks 0-7)
    if (blockIdx.x < NSTY) {
        int s = blockIdx.x, j = threadIdx.x;
        float a = b0[j];
        const float* e = emb + s * SDIM;
        #pragma unroll 8
        for (int d = 0; d < SDIM; d++) a += e[d] * W0[(3 + d) * HID + j];
        g_c0[s][j] = a;
    }
}

// ---------------- weight chunk streaming (k16 chunks, 16KB) ----------------
__device__ __forceinline__ void load_chunk(int g, uint32_t sb, int tid) {
    int l = g >> 4, kc = g & 15, bsel = g & 1;
    uint32_t dbase = sb + SO_WBUF + (uint32_t)bsel * 16384u;
    #pragma unroll
    for (int i = 0; i < 4; i++) {
        int idx = tid + i * 256;               // 0..1023 (16B units)
        int term = idx >> 9;                   // 8KB per term
        int r = idx & 511;
        const char* src = (const char*)&g_Wm[l][term][0] + kc * 8192 + r * 16;
        uint32_t dst = dbase + (uint32_t)term * 8192u + (uint32_t)r * 16u;
        CP_ASYNC16(dst, src);
    }
    CP_COMMIT();
}

// ---------------- main kernel ----------------
__global__ void __launch_bounds__(THREADS, 2)
nilut_mma(const float* __restrict__ rgb, const int* __restrict__ sidx,
          const float* __restrict__ W0,
          const float* __restrict__ b1, const float* __restrict__ b2,
          const float* __restrict__ W3, const float* __restrict__ b3,
          float* __restrict__ out, int HW)
{
    extern __shared__ __align__(128) char smem[];
    uint32_t sb = smem_to_u32(smem);
    float* w0s  = (float*)(smem + SO_W0);
    float* c0s  = (float*)(smem + SO_C0);
    float* b1s  = (float*)(smem + SO_B1);
    float* b2s  = (float*)(smem + SO_B2);
    float* w3s  = (float*)(smem + SO_W3);
    float* b3s  = (float*)(smem + SO_B3);
    float* pbuf = (float*)(smem + SO_PBUF);

    const int tid = threadIdx.x, wid = tid >> 5, lane = tid & 31;
    const int warp_m = wid >> 2, warp_n = wid & 3;   // 2 x 4 warp grid, 32x64 warp tile

    const long long base = (long long)blockIdx.x * MT;
    const int b = (int)(base / HW), hw0 = (int)(base % HW);
    const int style = sidx[b];

    // prefetch first two weight chunks (layer-1, k0-31)
    load_chunk(0, sb, tid);
    load_chunk(1, sb, tid);

    // stage small tensors
    for (int i = tid; i < 768; i += THREADS) w0s[i] = W0[i];
    c0s[tid] = g_c0[style][tid];
    b1s[tid] = b1[tid];
    b2s[tid] = b2[tid];
    for (int i = tid; i < 768; i += THREADS) { int c = i >> 8, k = i & 255; w3s[i] = W3[k * 3 + c]; }
    if (tid < 3) b3s[tid] = b3[tid];
    if (tid < 192) pbuf[tid] = 0.f;
    __syncthreads();

    // ---- layer 0: SIMT, write act hi/lo (4 threads per pixel, 64 n-cols each) ----
    {
        const int m = tid >> 2, q = tid & 3;
        const float r0 = rgb[((long long)b * 3 + 0) * HW + hw0 + m];
        const float r1 = rgb[((long long)b * 3 + 1) * HW + hw0 + m];
        const float r2 = rgb[((long long)b * 3 + 2) * HW + hw0 + m];
        uint32_t arow = (uint32_t)m * APITCHB + (uint32_t)q * 128u;  // byte offset (q*64 cols * 2B)
        #pragma unroll 4
        for (int i = 0; i < 32; i++) {
            int n = q * 64 + 2 * i;
            float z0 = c0s[n]     + r0 * w0s[n]     + r1 * w0s[256 + n]     + r2 * w0s[512 + n];
            float z1 = c0s[n + 1] + r0 * w0s[n + 1] + r1 * w0s[256 + n + 1] + r2 * w0s[512 + n + 1];
            float g0 = gelu_f(z0), g1 = gelu_f(z1);
            uint32_t hi = pack2(g0, g1);
            __nv_bfloat162 hv = *reinterpret_cast<__nv_bfloat162*>(&hi);
            uint32_t lo = pack2(g0 - __bfloat162float(hv.x), g1 - __bfloat162float(hv.y));
            *(uint32_t*)(smem + SO_ACTHI + arow + 4u * i) = hi;
            *(uint32_t*)(smem + SO_ACTLO + arow + 4u * i) = lo;
        }
    }

    // per-lane ldmatrix offsets
    const uint32_t arow_l = (uint32_t)((lane & 7) + ((lane >> 3) & 1) * 8);
    const uint32_t akoff  = (uint32_t)(((lane >> 4) & 1) * 8);

    float d[2][8][4];
    #pragma unroll
    for (int mf = 0; mf < 2; mf++)
        #pragma unroll
        for (int nb = 0; nb < 8; nb++)
            #pragma unroll
            for (int e = 0; e < 4; e++) d[mf][nb][e] = 0.f;

    // ---- layers 1 & 2: 32 k16-chunks total (16 per layer) ----
    for (int g = 0; g < 32; g++) {
        if (g == 31) { CP_WAIT0(); } else { CP_WAIT1(); }
        __syncthreads();
        const int bsel = g & 1;
        const int kc = g & 15;
        uint32_t ah[2][4], al[2][4];
        #pragma unroll
        for (int mf = 0; mf < 2; mf++) {
            uint32_t row = (uint32_t)(warp_m * 32 + mf * 16) + arow_l;
            uint32_t col = (uint32_t)(kc * 16) + akoff;
            uint32_t ad = sb + SO_ACTHI + row * APITCHB + col * 2u;
            LDSM4(ah[mf], ad);
            LDSM4(al[mf], ad + (SO_ACTLO - SO_ACTHI));
        }
        uint32_t wch = sb + SO_WBUF + (uint32_t)bsel * 16384u;
        #pragma unroll
        for (int nbp = 0; nbp < 4; nbp++) {
            uint32_t bd = wch + (uint32_t)((warp_n * 8 + nbp * 2) * 256) + (uint32_t)lane * 16u;
            uint32_t bh[4], bl[4];
            LDSM4(bh, bd);
            LDSM4(bl, bd + 8192u);
            #pragma unroll
            for (int h = 0; h < 2; h++) {
                #pragma unroll
                for (int mf = 0; mf < 2; mf++) {
                    float* dd = d[mf][nbp * 2 + h];
                    MMA_B16(dd, ah[mf], bh[2 * h], bh[2 * h + 1]);
                    MMA_B16(dd, al[mf], bh[2 * h], bh[2 * h + 1]);
                    MMA_B16(dd, ah[mf], bl[2 * h], bl[2 * h + 1]);
                }
            }
        }
        __syncthreads();
        if (g + 2 < 32) load_chunk(g + 2, sb, tid);

        if (g == 15) {
            // ---- mid epilogue: bias + GELU + split, write act hi/lo ----
            #pragma unroll
            for (int mf = 0; mf < 2; mf++) {
                #pragma unroll
                for (int nb = 0; nb < 8; nb++) {
                    int n0 = warp_n * 64 + nb * 8 + (lane & 3) * 2;
                    float bb0 = b1s[n0], bb1 = b1s[n0 + 1];
                    int mlow = warp_m * 32 + mf * 16 + (lane >> 2);
                    float g0 = gelu_f(d[mf][nb][0] + bb0);
                    float g1 = gelu_f(d[mf][nb][1] + bb1);
                    float g2 = gelu_f(d[mf][nb][2] + bb0);
                    float g3 = gelu_f(d[mf][nb][3] + bb1);
                    uint32_t hiA = pack2(g0, g1);
                    __nv_bfloat162 hA = *reinterpret_cast<__nv_bfloat162*>(&hiA);
                    uint32_t loA = pack2(g0 - __bfloat162float(hA.x), g1 - __bfloat162float(hA.y));
                    uint32_t hiB = pack2(g2, g3);
                    __nv_bfloat162 hB = *reinterpret_cast<__nv_bfloat162*>(&hiB);
                    uint32_t loB = pack2(g2 - __bfloat162float(hB.x), g3 - __bfloat162float(hB.y));
                    uint32_t offA = (uint32_t)mlow * APITCHB + (uint32_t)n0 * 2u;
                    uint32_t offB = offA + 8u * APITCHB;
                    *(uint32_t*)(smem + SO_ACTHI + offA) = hiA;
                    *(uint32_t*)(smem + SO_ACTLO + offA) = loA;
                    *(uint32_t*)(smem + SO_ACTHI + offB) = hiB;
                    *(uint32_t*)(smem + SO_ACTLO + offB) = loB;
                }
            }
            #pragma unroll
            for (int mf = 0; mf < 2; mf++)
                #pragma unroll
                for (int nb = 0; nb < 8; nb++)
                    #pragma unroll
                    for (int e = 0; e < 4; e++) d[mf][nb][e] = 0.f;
            // next iteration's leading __syncthreads orders these writes vs reads
        }
    }

    // ---- final epilogue: bias + GELU + layer3 dot + reduce ----
    #pragma unroll
    for (int mf = 0; mf < 2; mf++) {
        float pl0 = 0.f, pl1 = 0.f, pl2 = 0.f, ph0 = 0.f, ph1 = 0.f, ph2 = 0.f;
        #pragma unroll
        for (int nb = 0; nb < 8; nb++) {
            int n0 = warp_n * 64 + nb * 8 + (lane & 3) * 2;
            float bb0 = b2s[n0], bb1 = b2s[n0 + 1];
            float g0 = gelu_f(d[mf][nb][0] + bb0);
            float g1 = gelu_f(d[mf][nb][1] + bb1);
            float g2 = gelu_f(d[mf][nb][2] + bb0);
            float g3 = gelu_f(d[mf][nb][3] + bb1);
            float wa0 = w3s[n0], wa1 = w3s[n0 + 1];
            float wb0 = w3s[256 + n0], wb1 = w3s[256 + n0 + 1];
            float wc0 = w3s[512 + n0], wc1 = w3s[512 + n0 + 1];
            pl0 += g0 * wa0 + g1 * wa1;  ph0 += g2 * wa0 + g3 * wa1;
            pl1 += g0 * wb0 + g1 * wb1;  ph1 += g2 * wb0 + g3 * wb1;
            pl2 += g0 * wc0 + g1 * wc1;  ph2 += g2 * wc0 + g3 * wc1;
        }
        #pragma unroll
        for (int s = 1; s <= 2; s <<= 1) {
            pl0 += __shfl_xor_sync(0xFFFFFFFF, pl0, s);
            pl1 += __shfl_xor_sync(0xFFFFFFFF, pl1, s);
            pl2 += __shfl_xor_sync(0xFFFFFFFF, pl2, s);
            ph0 += __shfl_xor_sync(0xFFFFFFFF, ph0, s);
            ph1 += __shfl_xor_sync(0xFFFFFFFF, ph1, s);
            ph2 += __shfl_xor_sync(0xFFFFFFFF, ph2, s);
        }
        if ((lane & 3) == 0) {
            int mlow = warp_m * 32 + mf * 16 + (lane >> 2);
            atomicAdd(&pbuf[mlow], pl0);
            atomicAdd(&pbuf[64 + mlow], pl1);
            atomicAdd(&pbuf[128 + mlow], pl2);
            atomicAdd(&pbuf[mlow + 8], ph0);
            atomicAdd(&pbuf[64 + mlow + 8], ph1);
            atomicAdd(&pbuf[128 + mlow + 8], ph2);
        }
    }
    __syncthreads();
    if (tid < 192) {
        const int c = tid >> 6, m = tid & 63;
        float z = pbuf[c * 64 + m] + b3s[c];
        out[((long long)b * 3 + c) * HW + hw0 + m] = __fdividef(1.0f, 1.0f + __expf(-z));
    }
}

// ---------------- launch ----------------
extern "C" void kernel_launch(void* const* d_in, const int* in_sizes, int n_in,
                              void* d_out, int out_size) {
    const float* rgb  = (const float*)d_in[0];
    const int*   sidx = (const int*)d_in[1];
    const float* emb  = (const float*)d_in[2];
    const float* W0   = (const float*)d_in[3];
    const float* b0   = (const float*)d_in[4];
    const float* W1   = (const float*)d_in[5];
    const float* b1   = (const float*)d_in[6];
    const float* W2   = (const float*)d_in[7];
    const float* b2   = (const float*)d_in[8];
    const float* W3   = (const float*)d_in[9];
    const float* b3   = (const float*)d_in[10];
    float* out = (float*)d_out;

    const int B = in_sizes[1];
    const long long HW = (long long)in_sizes[0] / (3LL * B);
    const long long N  = (long long)B * HW;

    static bool attr_set = false;
    if (!attr_set) {
        cudaFuncSetAttribute(nilut_mma, cudaFuncAttributeMaxDynamicSharedMemorySize, SMEM_TOTAL);
        attr_set = true;
    }

    prep_kernel<<<512, HID>>>(emb, W0, b0, W1, W2);
    nilut_mma<<<(unsigned)(N / MT), THREADS, SMEM_TOTAL>>>(
        rgb, sidx, W0, b1, b2, W3, b3, out, (int)HW);
}

// round 8
// speedup vs baseline: 3.2093x; 1.2445x over previous
#include <cuda_runtime.h>
#include <cuda_fp16.h>
#include <math.h>
#include <stdint.h>

#define HID 256
#define NSTY 8
#define SDIM 64
#define MT 64
#define THREADS 256

// activation SMEM pitch: 264 fp16 = 528B (conflict-staggered ldmatrix rows)
#define APITCHB 528

// SMEM layout (bytes)
#define SO_ACT   0                // 64*528 = 33792 (single fp16 act)
#define SO_WBUF  33792            // 4 stages x 16KB (hi 8KB + lo 8KB per stage)
#define SO_W0    99328            // 3*256 f32
#define SO_C0    102400           // 256 f32
#define SO_B1    103424           // 256 f32
#define SO_B2    104448           // 256 f32
#define SO_W3    105472           // 3*256 f32 (w3s[c*256+k])
#define SO_B3    108544           // 3 f32 (+pad)
#define SO_PBUF  108560           // 3*64 f32
#define SMEM_TOTAL 109328         // <= 113.5KB -> 2 CTAs/SM

// ---------------- device globals ----------------
__device__ float g_c0[NSTY][HID];
// [layer][term(hi/lo)] x 65536 fp16 (256x256), laid out as [kc(16)][nb(32)][sub(2)][row(8)][col(8)]
__device__ __align__(16) __half g_Wm[2][2][65536];

// ---------------- helpers ----------------
__device__ __forceinline__ uint32_t smem_to_u32(const void* p) {
    uint32_t a;
    asm("{ .reg .u64 t; cvta.to.shared.u64 t, %1; cvt.u32.u64 %0, t; }" : "=r"(a) : "l"(p));
    return a;
}
#define LDSM4(R, addr) \
    asm volatile("ldmatrix.sync.aligned.m8n8.x4.shared.b16 {%0,%1,%2,%3}, [%4];" \
        : "=r"((R)[0]), "=r"((R)[1]), "=r"((R)[2]), "=r"((R)[3]) : "r"(addr))
#define MMA_F16(dd, a, b0_, b1_) \
    asm volatile("mma.sync.aligned.m16n8k16.row.col.f32.f16.f16.f32 " \
        "{%0,%1,%2,%3}, {%4,%5,%6,%7}, {%8,%9}, {%0,%1,%2,%3};" \
        : "+f"((dd)[0]), "+f"((dd)[1]), "+f"((dd)[2]), "+f"((dd)[3]) \
        : "r"((a)[0]), "r"((a)[1]), "r"((a)[2]), "r"((a)[3]), "r"(b0_), "r"(b1_))
#define CP_ASYNC16(dst, src) \
    asm volatile("cp.async.cg.shared.global [%0], [%1], 16;" :: "r"(dst), "l"(src) : "memory")
#define CP_COMMIT() asm volatile("cp.async.commit_group;" ::: "memory")
#define CP_WAIT2()  asm volatile("cp.async.wait_group 2;" ::: "memory")
#define CP_WAIT1()  asm volatile("cp.async.wait_group 1;" ::: "memory")
#define CP_WAIT0()  asm volatile("cp.async.wait_group 0;" ::: "memory")

__device__ __forceinline__ float gelu_f(float x) {
    // 0.5*x*(1+erf(x/sqrt(2))), erf via Abramowitz-Stegun 7.1.26 (|err|<=1.5e-7)
    float u  = x * 0.70710678118654752f;
    float au = fabsf(u);
    float t  = __fdividef(1.0f, fmaf(0.3275911f, au, 1.0f));
    float p  = t * fmaf(t, fmaf(t, fmaf(t, fmaf(t, 1.061405429f, -1.453152027f),
                                        1.421413741f), -0.284496736f), 0.254829592f);
    float er = 1.0f - p * __expf(-au * au);
    er = copysignf(er, u);
    return 0.5f * x * (1.0f + er);
}
__device__ __forceinline__ uint32_t pack2h(float a, float b) {
    __half2 t = __floats2half2_rn(a, b);
    return *reinterpret_cast<uint32_t*>(&t);
}

// ---------------- merged prologue kernel ----------------
__global__ void prep_kernel(const float* __restrict__ emb,
                            const float* __restrict__ W0,
                            const float* __restrict__ b0,
                            const float* __restrict__ W1,
                            const float* __restrict__ W2) {
    // weight split (fp16 hi + residual lo) + fragment rearrange
    int l = blockIdx.x >> 8, n = blockIdx.x & 255, k = threadIdx.x;
    const float* Ws = l ? W2 : W1;
    float w = Ws[k * HID + n];
    __half h = __float2half_rn(w);
    float lo = w - __half2float(h);
    int off = ((((k >> 4) * 32 + (n >> 3)) * 2 + ((k >> 3) & 1)) * 8 + (n & 7)) * 8 + (k & 7);
    g_Wm[l][0][off] = h;
    g_Wm[l][1][off] = __float2half_rn(lo);

    // folded per-style bias (blocks 0-7)
    if (blockIdx.x < NSTY) {
        int s = blockIdx.x, j = threadIdx.x;
        float a = b0[j];
        const float* e = emb + s * SDIM;
        #pragma unroll 8
        for (int d = 0; d < SDIM; d++) a += e[d] * W0[(3 + d) * HID + j];
        g_c0[s][j] = a;
    }
}

// ---------------- weight chunk streaming (k16 chunks, 16KB: hi 8KB + lo 8KB) ----------------
__device__ __forceinline__ void load_chunk(int g, uint32_t sb, int tid) {
    int l = g >> 4, kc = g & 15;
    uint32_t dbase = sb + SO_WBUF + (uint32_t)(g & 3) * 16384u;
    #pragma unroll
    for (int i = 0; i < 4; i++) {
        int idx = tid + i * 256;               // 0..1023 (16B units)
        int term = idx >> 9;                   // 8KB per term
        int r = idx & 511;
        const char* src = (const char*)&g_Wm[l][term][0] + kc * 8192 + r * 16;
        uint32_t dst = dbase + (uint32_t)term * 8192u + (uint32_t)r * 16u;
        CP_ASYNC16(dst, src);
    }
    CP_COMMIT();
}

// ---------------- main kernel ----------------
__global__ void __launch_bounds__(THREADS, 2)
nilut_mma(const float* __restrict__ rgb, const int* __restrict__ sidx,
          const float* __restrict__ W0,
          const float* __restrict__ b1, const float* __restrict__ b2,
          const float* __restrict__ W3, const float* __restrict__ b3,
          float* __restrict__ out, int HW)
{
    extern __shared__ __align__(128) char smem[];
    uint32_t sb = smem_to_u32(smem);
    float* w0s  = (float*)(smem + SO_W0);
    float* c0s  = (float*)(smem + SO_C0);
    float* b1s  = (float*)(smem + SO_B1);
    float* b2s  = (float*)(smem + SO_B2);
    float* w3s  = (float*)(smem + SO_W3);
    float* b3s  = (float*)(smem + SO_B3);
    float* pbuf = (float*)(smem + SO_PBUF);

    const int tid = threadIdx.x, wid = tid >> 5, lane = tid & 31;
    const int warp_m = wid >> 2, warp_n = wid & 3;   // 2 x 4 warp grid, 32x64 warp tile

    const long long base = (long long)blockIdx.x * MT;
    const int b = (int)(base / HW), hw0 = (int)(base % HW);
    const int style = sidx[b];

    // prefetch first three weight chunks (layer-1, k0-47)
    load_chunk(0, sb, tid);
    load_chunk(1, sb, tid);
    load_chunk(2, sb, tid);

    // stage small tensors
    for (int i = tid; i < 768; i += THREADS) w0s[i] = W0[i];
    c0s[tid] = g_c0[style][tid];
    b1s[tid] = b1[tid];
    b2s[tid] = b2[tid];
    for (int i = tid; i < 768; i += THREADS) { int c = i >> 8, k = i & 255; w3s[i] = W3[k * 3 + c]; }
    if (tid < 3) b3s[tid] = b3[tid];
    if (tid < 192) pbuf[tid] = 0.f;
    __syncthreads();

    // ---- layer 0: SIMT, write act fp16 (4 threads per pixel, 64 n-cols each) ----
    {
        const int m = tid >> 2, q = tid & 3;
        const float r0 = rgb[((long long)b * 3 + 0) * HW + hw0 + m];
        const float r1 = rgb[((long long)b * 3 + 1) * HW + hw0 + m];
        const float r2 = rgb[((long long)b * 3 + 2) * HW + hw0 + m];
        uint32_t arow = (uint32_t)m * APITCHB + (uint32_t)q * 128u;  // byte offset (q*64 cols * 2B)
        #pragma unroll 4
        for (int i = 0; i < 32; i++) {
            int n = q * 64 + 2 * i;
            float z0 = c0s[n]     + r0 * w0s[n]     + r1 * w0s[256 + n]     + r2 * w0s[512 + n];
            float z1 = c0s[n + 1] + r0 * w0s[n + 1] + r1 * w0s[256 + n + 1] + r2 * w0s[512 + n + 1];
            *(uint32_t*)(smem + SO_ACT + arow + 4u * i) = pack2h(gelu_f(z0), gelu_f(z1));
        }
    }

    // per-lane ldmatrix offsets
    const uint32_t arow_l = (uint32_t)((lane & 7) + ((lane >> 3) & 1) * 8);
    const uint32_t akoff  = (uint32_t)(((lane >> 4) & 1) * 8);

    float d[2][8][4];
    #pragma unroll
    for (int mf = 0; mf < 2; mf++)
        #pragma unroll
        for (int nb = 0; nb < 8; nb++)
            #pragma unroll
            for (int e = 0; e < 4; e++) d[mf][nb][e] = 0.f;

    // ---- layers 1 & 2: 32 k16-chunks, 4-stage pipeline, ONE barrier per chunk ----
    for (int g = 0; g < 32; g++) {
        if (g <= 29) { CP_WAIT2(); } else if (g == 30) { CP_WAIT1(); } else { CP_WAIT0(); }
        __syncthreads();      // chunk g visible to all; all warps done with chunk (g+3)%4's buffer
        if (g + 3 < 32) load_chunk(g + 3, sb, tid);

        const int kc = g & 15;
        uint32_t buf = sb + SO_WBUF + (uint32_t)(g & 3) * 16384u;
        uint32_t ah[2][4];
        #pragma unroll
        for (int mf = 0; mf < 2; mf++) {
            uint32_t row = (uint32_t)(warp_m * 32 + mf * 16) + arow_l;
            uint32_t col = (uint32_t)(kc * 16) + akoff;
            LDSM4(ah[mf], sb + SO_ACT + row * APITCHB + col * 2u);
        }
        #pragma unroll
        for (int nbp = 0; nbp < 4; nbp++) {
            uint32_t bd = buf + (uint32_t)((warp_n * 8 + nbp * 2) * 256) + (uint32_t)lane * 16u;
            uint32_t bh[4], bl[4];
            LDSM4(bh, bd);
            LDSM4(bl, bd + 8192u);
            #pragma unroll
            for (int h = 0; h < 2; h++) {
                #pragma unroll
                for (int mf = 0; mf < 2; mf++) {
                    float* dd = d[mf][nbp * 2 + h];
                    MMA_F16(dd, ah[mf], bh[2 * h], bh[2 * h + 1]);
                    MMA_F16(dd, ah[mf], bl[2 * h], bl[2 * h + 1]);
                }
            }
        }

        if (g == 15) {
            __syncthreads();   // all warps done reading layer-1 act before overwrite
            // ---- mid epilogue: bias + GELU, write act fp16 ----
            #pragma unroll
            for (int mf = 0; mf < 2; mf++) {
                #pragma unroll
                for (int nb = 0; nb < 8; nb++) {
                    int n0 = warp_n * 64 + nb * 8 + (lane & 3) * 2;
                    float bb0 = b1s[n0], bb1 = b1s[n0 + 1];
                    int mlow = warp_m * 32 + mf * 16 + (lane >> 2);
                    float g0 = gelu_f(d[mf][nb][0] + bb0);
                    float g1 = gelu_f(d[mf][nb][1] + bb1);
                    float g2 = gelu_f(d[mf][nb][2] + bb0);
                    float g3 = gelu_f(d[mf][nb][3] + bb1);
                    uint32_t offA = (uint32_t)mlow * APITCHB + (uint32_t)n0 * 2u;
                    *(uint32_t*)(smem + SO_ACT + offA) = pack2h(g0, g1);
                    *(uint32_t*)(smem + SO_ACT + offA + 8u * APITCHB) = pack2h(g2, g3);
                }
            }
            #pragma unroll
            for (int mf = 0; mf < 2; mf++)
                #pragma unroll
                for (int nb = 0; nb < 8; nb++)
                    #pragma unroll
                    for (int e = 0; e < 4; e++) d[mf][nb][e] = 0.f;
            // next iteration's leading __syncthreads orders these writes vs reads
        }
    }

    // ---- final epilogue: bias + GELU + layer3 dot + reduce ----
    #pragma unroll
    for (int mf = 0; mf < 2; mf++) {
        float pl0 = 0.f, pl1 = 0.f, pl2 = 0.f, ph0 = 0.f, ph1 = 0.f, ph2 = 0.f;
        #pragma unroll
        for (int nb = 0; nb < 8; nb++) {
            int n0 = warp_n * 64 + nb * 8 + (lane & 3) * 2;
            float bb0 = b2s[n0], bb1 = b2s[n0 + 1];
            float g0 = gelu_f(d[mf][nb][0] + bb0);
            float g1 = gelu_f(d[mf][nb][1] + bb1);
            float g2 = gelu_f(d[mf][nb][2] + bb0);
            float g3 = gelu_f(d[mf][nb][3] + bb1);
            float wa0 = w3s[n0], wa1 = w3s[n0 + 1];
            float wb0 = w3s[256 + n0], wb1 = w3s[256 + n0 + 1];
            float wc0 = w3s[512 + n0], wc1 = w3s[512 + n0 + 1];
            pl0 += g0 * wa0 + g1 * wa1;  ph0 += g2 * wa0 + g3 * wa1;
            pl1 += g0 * wb0 + g1 * wb1;  ph1 += g2 * wb0 + g3 * wb1;
            pl2 += g0 * wc0 + g1 * wc1;  ph2 += g2 * wc0 + g3 * wc1;
        }
        #pragma unroll
        for (int s = 1; s <= 2; s <<= 1) {
            pl0 += __shfl_xor_sync(0xFFFFFFFF, pl0, s);
            pl1 += __shfl_xor_sync(0xFFFFFFFF, pl1, s);
            pl2 += __shfl_xor_sync(0xFFFFFFFF, pl2, s);
            ph0 += __shfl_xor_sync(0xFFFFFFFF, ph0, s);
            ph1 += __shfl_xor_sync(0xFFFFFFFF, ph1, s);
            ph2 += __shfl_xor_sync(0xFFFFFFFF, ph2, s);
        }
        if ((lane & 3) == 0) {
            int mlow = warp_m * 32 + mf * 16 + (lane >> 2);
            atomicAdd(&pbuf[mlow], pl0);
            atomicAdd(&pbuf[64 + mlow], pl1);
            atomicAdd(&pbuf[128 + mlow], pl2);
            atomicAdd(&pbuf[mlow + 8], ph0);
            atomicAdd(&pbuf[64 + mlow + 8], ph1);
            atomicAdd(&pbuf[128 + mlow + 8], ph2);
        }
    }
    __syncthreads();
    if (tid < 192) {
        const int c = tid >> 6, m = tid & 63;
        float z = pbuf[c * 64 + m] + b3s[c];
        out[((long long)b * 3 + c) * HW + hw0 + m] = __fdividef(1.0f, 1.0f + __expf(-z));
    }
}

// ---------------- launch ----------------
extern "C" void kernel_launch(void* const* d_in, const int* in_sizes, int n_in,
                              void* d_out, int out_size) {
    const float* rgb  = (const float*)d_in[0];
    const int*   sidx = (const int*)d_in[1];
    const float* emb  = (const float*)d_in[2];
    const float* W0   = (const float*)d_in[3];
    const float* b0   = (const float*)d_in[4];
    const float* W1   = (const float*)d_in[5];
    const float* b1   = (const float*)d_in[6];
    const float* W2   = (const float*)d_in[7];
    const float* b2   = (const float*)d_in[8];
    const float* W3   = (const float*)d_in[9];
    const float* b3   = (const float*)d_in[10];
    float* out = (float*)d_out;

    const int B = in_sizes[1];
    const long long HW = (long long)in_sizes[0] / (3LL * B);
    const long long N  = (long long)B * HW;

    static bool attr_set = false;
    if (!attr_set) {
        cudaFuncSetAttribute(nilut_mma, cudaFuncAttributeMaxDynamicSharedMemorySize, SMEM_TOTAL);
        attr_set = true;
    }

    prep_kernel<<<512, HID>>>(emb, W0, b0, W1, W2);
    nilut_mma<<<(unsigned)(N / MT), THREADS, SMEM_TOTAL>>>(
        rgb, sidx, W0, b1, b2, W3, b3, out, (int)HW);
}

// round 9
// speedup vs baseline: 3.8377x; 1.1958x over previous
#include <cuda_runtime.h>
#include <cuda_fp16.h>
#include <math.h>
#include <stdint.h>

#define HID 256
#define NSTY 8
#define SDIM 64
#define MT 64
#define THREADS 256

// activation SMEM pitch: 264 fp16 = 528B (conflict-staggered ldmatrix rows)
#define APITCHB 528

// SMEM layout (bytes)
#define SO_ACT   0                // 64*528 = 33792 (single fp16 act)
#define SO_WBUF  33792            // 4 stages x 16KB (hi 8KB + lo 8KB per stage)
#define SO_W0    99328            // 3*256 f32
#define SO_C0    102400           // 256 f32
#define SO_B1    103424           // 256 f32
#define SO_B2    104448           // 256 f32
#define SO_W3    105472           // 3*256 f32 (w3s[c*256+k])
#define SO_B3    108544           // 3 f32 (+pad)
#define SO_PBUF  108560           // 3*64 f32
#define SMEM_TOTAL 109328         // <= 113.5KB -> 2 CTAs/SM

// ---------------- device globals ----------------
__device__ float g_c0[NSTY][HID];
// [layer][term(hi/lo)] x 65536 fp16 (256x256), laid out as [kc(16)][nb(32)][sub(2)][row(8)][col(8)]
__device__ __align__(16) __half g_Wm[2][2][65536];

// ---------------- helpers ----------------
__device__ __forceinline__ uint32_t smem_to_u32(const void* p) {
    uint32_t a;
    asm("{ .reg .u64 t; cvta.to.shared.u64 t, %1; cvt.u32.u64 %0, t; }" : "=r"(a) : "l"(p));
    return a;
}
#define LDSM4(R, addr) \
    asm volatile("ldmatrix.sync.aligned.m8n8.x4.shared.b16 {%0,%1,%2,%3}, [%4];" \
        : "=r"((R)[0]), "=r"((R)[1]), "=r"((R)[2]), "=r"((R)[3]) : "r"(addr))
#define MMA_F16(dd, a, b0_, b1_) \
    asm volatile("mma.sync.aligned.m16n8k16.row.col.f32.f16.f16.f32 " \
        "{%0,%1,%2,%3}, {%4,%5,%6,%7}, {%8,%9}, {%0,%1,%2,%3};" \
        : "+f"((dd)[0]), "+f"((dd)[1]), "+f"((dd)[2]), "+f"((dd)[3]) \
        : "r"((a)[0]), "r"((a)[1]), "r"((a)[2]), "r"((a)[3]), "r"(b0_), "r"(b1_))
#define CP_ASYNC16(dst, src) \
    asm volatile("cp.async.cg.shared.global [%0], [%1], 16;" :: "r"(dst), "l"(src) : "memory")
#define CP_COMMIT() asm volatile("cp.async.commit_group;" ::: "memory")
#define CP_WAIT2()  asm volatile("cp.async.wait_group 2;" ::: "memory")
#define CP_WAIT1()  asm volatile("cp.async.wait_group 1;" ::: "memory")
#define CP_WAIT0()  asm volatile("cp.async.wait_group 0;" ::: "memory")

__device__ __forceinline__ float gelu_f(float x) {
    // 0.5*x*(1+erf(x/sqrt(2))), erf via Abramowitz-Stegun 7.1.26 (|err|<=1.5e-7)
    float u  = x * 0.70710678118654752f;
    float au = fabsf(u);
    float t  = __fdividef(1.0f, fmaf(0.3275911f, au, 1.0f));
    float p  = t * fmaf(t, fmaf(t, fmaf(t, fmaf(t, 1.061405429f, -1.453152027f),
                                        1.421413741f), -0.284496736f), 0.254829592f);
    float er = 1.0f - p * __expf(-au * au);
    er = copysignf(er, u);
    return 0.5f * x * (1.0f + er);
}
__device__ __forceinline__ uint32_t pack2h(float a, float b) {
    __half2 t = __floats2half2_rn(a, b);
    return *reinterpret_cast<uint32_t*>(&t);
}

// ---------------- merged prologue kernel ----------------
__global__ void prep_kernel(const float* __restrict__ emb,
                            const float* __restrict__ W0,
                            const float* __restrict__ b0,
                            const float* __restrict__ W1,
                            const float* __restrict__ W2) {
    // weight split (fp16 hi + residual lo) + fragment rearrange
    int l = blockIdx.x >> 8, n = blockIdx.x & 255, k = threadIdx.x;
    const float* Ws = l ? W2 : W1;
    float w = Ws[k * HID + n];
    __half h = __float2half_rn(w);
    float lo = w - __half2float(h);
    int off = ((((k >> 4) * 32 + (n >> 3)) * 2 + ((k >> 3) & 1)) * 8 + (n & 7)) * 8 + (k & 7);
    g_Wm[l][0][off] = h;
    g_Wm[l][1][off] = __float2half_rn(lo);

    // folded per-style bias (blocks 0-7)
    if (blockIdx.x < NSTY) {
        int s = blockIdx.x, j = threadIdx.x;
        float a = b0[j];
        const float* e = emb + s * SDIM;
        #pragma unroll 8
        for (int d = 0; d < SDIM; d++) a += e[d] * W0[(3 + d) * HID + j];
        g_c0[s][j] = a;
    }
}

// ---------------- weight chunk streaming (k16 chunks, 16KB: hi 8KB + lo 8KB) ----------------
__device__ __forceinline__ void load_chunk(int g, uint32_t sb, int tid) {
    int l = g >> 4, kc = g & 15;
    uint32_t dbase = sb + SO_WBUF + (uint32_t)(g & 3) * 16384u;
    #pragma unroll
    for (int i = 0; i < 4; i++) {
        int idx = tid + i * 256;               // 0..1023 (16B units)
        int term = idx >> 9;                   // 8KB per term
        int r = idx & 511;
        const char* src = (const char*)&g_Wm[l][term][0] + kc * 8192 + r * 16;
        uint32_t dst = dbase + (uint32_t)term * 8192u + (uint32_t)r * 16u;
        CP_ASYNC16(dst, src);
    }
    CP_COMMIT();
}

// ---------------- main kernel ----------------
__global__ void __launch_bounds__(THREADS, 2)
nilut_mma(const float* __restrict__ rgb, const int* __restrict__ sidx,
          const float* __restrict__ W0,
          const float* __restrict__ b1, const float* __restrict__ b2,
          const float* __restrict__ W3, const float* __restrict__ b3,
          float* __restrict__ out, int HW)
{
    extern __shared__ __align__(128) char smem[];
    uint32_t sb = smem_to_u32(smem);
    float* w0s  = (float*)(smem + SO_W0);
    float* c0s  = (float*)(smem + SO_C0);
    float* b1s  = (float*)(smem + SO_B1);
    float* b2s  = (float*)(smem + SO_B2);
    float* w3s  = (float*)(smem + SO_W3);
    float* b3s  = (float*)(smem + SO_B3);
    float* pbuf = (float*)(smem + SO_PBUF);

    const int tid = threadIdx.x, wid = tid >> 5, lane = tid & 31;
    const int warp_m = wid >> 2, warp_n = wid & 3;   // 2 x 4 warp grid, 32x64 warp tile

    const long long base = (long long)blockIdx.x * MT;
    const int b = (int)(base / HW), hw0 = (int)(base % HW);
    const int style = sidx[b];

    // prefetch first three weight chunks (layer-1, k0-47)
    load_chunk(0, sb, tid);
    load_chunk(1, sb, tid);
    load_chunk(2, sb, tid);

    // stage small tensors
    for (int i = tid; i < 768; i += THREADS) w0s[i] = W0[i];
    c0s[tid] = g_c0[style][tid];
    b1s[tid] = b1[tid];
    b2s[tid] = b2[tid];
    for (int i = tid; i < 768; i += THREADS) { int c = i >> 8, k = i & 255; w3s[i] = W3[k * 3 + c]; }
    if (tid < 3) b3s[tid] = b3[tid];
    if (tid < 192) pbuf[tid] = 0.f;
    __syncthreads();

    // ---- layer 0: SIMT, write act fp16 (4 threads per pixel, 64 n-cols each) ----
    {
        const int m = tid >> 2, q = tid & 3;
        const float r0 = rgb[((long long)b * 3 + 0) * HW + hw0 + m];
        const float r1 = rgb[((long long)b * 3 + 1) * HW + hw0 + m];
        const float r2 = rgb[((long long)b * 3 + 2) * HW + hw0 + m];
        uint32_t arow = (uint32_t)m * APITCHB + (uint32_t)q * 128u;  // byte offset (q*64 cols * 2B)
        #pragma unroll 4
        for (int i = 0; i < 32; i++) {
            int n = q * 64 + 2 * i;
            float z0 = c0s[n]     + r0 * w0s[n]     + r1 * w0s[256 + n]     + r2 * w0s[512 + n];
            float z1 = c0s[n + 1] + r0 * w0s[n + 1] + r1 * w0s[256 + n + 1] + r2 * w0s[512 + n + 1];
            *(uint32_t*)(smem + SO_ACT + arow + 4u * i) = pack2h(gelu_f(z0), gelu_f(z1));
        }
    }

    // per-lane ldmatrix offsets
    const uint32_t arow_l = (uint32_t)((lane & 7) + ((lane >> 3) & 1) * 8);
    const uint32_t akoff  = (uint32_t)(((lane >> 4) & 1) * 8);

    float d[2][8][4];
    #pragma unroll
    for (int mf = 0; mf < 2; mf++)
        #pragma unroll
        for (int nb = 0; nb < 8; nb++)
            #pragma unroll
            for (int e = 0; e < 4; e++) d[mf][nb][e] = 0.f;

    // ---- layer 1: chunks 0-15, hi+lo terms, 4-stage pipeline, 1 barrier/chunk ----
    #pragma unroll
    for (int g = 0; g < 16; g++) {
        CP_WAIT2();
        __syncthreads();      // chunk g visible; all warps done with stage (g+3)&3
        load_chunk(g + 3, sb, tid);

        uint32_t buf = sb + SO_WBUF + (uint32_t)(g & 3) * 16384u;
        uint32_t ah[2][4];
        #pragma unroll
        for (int mf = 0; mf < 2; mf++) {
            uint32_t row = (uint32_t)(warp_m * 32 + mf * 16) + arow_l;
            uint32_t col = (uint32_t)(g * 16) + akoff;
            LDSM4(ah[mf], sb + SO_ACT + row * APITCHB + col * 2u);
        }
        #pragma unroll
        for (int nbp = 0; nbp < 4; nbp++) {
            uint32_t bd = buf + (uint32_t)((warp_n * 8 + nbp * 2) * 256) + (uint32_t)lane * 16u;
            uint32_t bh[4], bl[4];
            LDSM4(bh, bd);
            LDSM4(bl, bd + 8192u);
            // hi block (4 distinct accumulators), then lo block: RAW distance = 4 MMAs
            MMA_F16(d[0][nbp * 2 + 0], ah[0], bh[0], bh[1]);
            MMA_F16(d[1][nbp * 2 + 0], ah[1], bh[0], bh[1]);
            MMA_F16(d[0][nbp * 2 + 1], ah[0], bh[2], bh[3]);
            MMA_F16(d[1][nbp * 2 + 1], ah[1], bh[2], bh[3]);
            MMA_F16(d[0][nbp * 2 + 0], ah[0], bl[0], bl[1]);
            MMA_F16(d[1][nbp * 2 + 0], ah[1], bl[0], bl[1]);
            MMA_F16(d[0][nbp * 2 + 1], ah[0], bl[2], bl[3]);
            MMA_F16(d[1][nbp * 2 + 1], ah[1], bl[2], bl[3]);
        }
    }

    // ---- mid epilogue: bias + GELU, write act fp16 ----
    __syncthreads();   // all warps done reading layer-1 act (chunk-15 LDSM) before overwrite
    #pragma unroll
    for (int mf = 0; mf < 2; mf++) {
        #pragma unroll
        for (int nb = 0; nb < 8; nb++) {
            int n0 = warp_n * 64 + nb * 8 + (lane & 3) * 2;
            float bb0 = b1s[n0], bb1 = b1s[n0 + 1];
            int mlow = warp_m * 32 + mf * 16 + (lane >> 2);
            float g0 = gelu_f(d[mf][nb][0] + bb0);
            float g1 = gelu_f(d[mf][nb][1] + bb1);
            float g2 = gelu_f(d[mf][nb][2] + bb0);
            float g3 = gelu_f(d[mf][nb][3] + bb1);
            uint32_t offA = (uint32_t)mlow * APITCHB + (uint32_t)n0 * 2u;
            *(uint32_t*)(smem + SO_ACT + offA) = pack2h(g0, g1);
            *(uint32_t*)(smem + SO_ACT + offA + 8u * APITCHB) = pack2h(g2, g3);
        }
    }
    #pragma unroll
    for (int mf = 0; mf < 2; mf++)
        #pragma unroll
        for (int nb = 0; nb < 8; nb++)
            #pragma unroll
            for (int e = 0; e < 4; e++) d[mf][nb][e] = 0.f;
    // layer-2 loop's first __syncthreads orders these writes vs LDSM reads

    // ---- layer 2: chunks 16-31, hi term only (fp16 weight quant ~1.4e-4, within budget) ----
    #pragma unroll
    for (int g = 16; g < 32; g++) {
        if (g <= 29) { CP_WAIT2(); } else if (g == 30) { CP_WAIT1(); } else { CP_WAIT0(); }
        __syncthreads();
        if (g + 3 < 32) load_chunk(g + 3, sb, tid);

        const int kc = g & 15;
        uint32_t buf = sb + SO_WBUF + (uint32_t)(g & 3) * 16384u;
        uint32_t ah[2][4];
        #pragma unroll
        for (int mf = 0; mf < 2; mf++) {
            uint32_t row = (uint32_t)(warp_m * 32 + mf * 16) + arow_l;
            uint32_t col = (uint32_t)(kc * 16) + akoff;
            LDSM4(ah[mf], sb + SO_ACT + row * APITCHB + col * 2u);
        }
        #pragma unroll
        for (int nbp = 0; nbp < 4; nbp++) {
            uint32_t bd = buf + (uint32_t)((warp_n * 8 + nbp * 2) * 256) + (uint32_t)lane * 16u;
            uint32_t bh[4];
            LDSM4(bh, bd);
            MMA_F16(d[0][nbp * 2 + 0], ah[0], bh[0], bh[1]);
            MMA_F16(d[1][nbp * 2 + 0], ah[1], bh[0], bh[1]);
            MMA_F16(d[0][nbp * 2 + 1], ah[0], bh[2], bh[3]);
            MMA_F16(d[1][nbp * 2 + 1], ah[1], bh[2], bh[3]);
        }
    }

    // ---- final epilogue: bias + GELU + layer3 dot + reduce ----
    #pragma unroll
    for (int mf = 0; mf < 2; mf++) {
        float pl0 = 0.f, pl1 = 0.f, pl2 = 0.f, ph0 = 0.f, ph1 = 0.f, ph2 = 0.f;
        #pragma unroll
        for (int nb = 0; nb < 8; nb++) {
            int n0 = warp_n * 64 + nb * 8 + (lane & 3) * 2;
            float bb0 = b2s[n0], bb1 = b2s[n0 + 1];
            float g0 = gelu_f(d[mf][nb][0] + bb0);
            float g1 = gelu_f(d[mf][nb][1] + bb1);
            float g2 = gelu_f(d[mf][nb][2] + bb0);
            float g3 = gelu_f(d[mf][nb][3] + bb1);
            float wa0 = w3s[n0], wa1 = w3s[n0 + 1];
            float wb0 = w3s[256 + n0], wb1 = w3s[256 + n0 + 1];
            float wc0 = w3s[512 + n0], wc1 = w3s[512 + n0 + 1];
            pl0 += g0 * wa0 + g1 * wa1;  ph0 += g2 * wa0 + g3 * wa1;
            pl1 += g0 * wb0 + g1 * wb1;  ph1 += g2 * wb0 + g3 * wb1;
            pl2 += g0 * wc0 + g1 * wc1;  ph2 += g2 * wc0 + g3 * wc1;
        }
        #pragma unroll
        for (int s = 1; s <= 2; s <<= 1) {
            pl0 += __shfl_xor_sync(0xFFFFFFFF, pl0, s);
            pl1 += __shfl_xor_sync(0xFFFFFFFF, pl1, s);
            pl2 += __shfl_xor_sync(0xFFFFFFFF, pl2, s);
            ph0 += __shfl_xor_sync(0xFFFFFFFF, ph0, s);
            ph1 += __shfl_xor_sync(0xFFFFFFFF, ph1, s);
            ph2 += __shfl_xor_sync(0xFFFFFFFF, ph2, s);
        }
        if ((lane & 3) == 0) {
            int mlow = warp_m * 32 + mf * 16 + (lane >> 2);
            atomicAdd(&pbuf[mlow], pl0);
            atomicAdd(&pbuf[64 + mlow], pl1);
            atomicAdd(&pbuf[128 + mlow], pl2);
            atomicAdd(&pbuf[mlow + 8], ph0);
            atomicAdd(&pbuf[64 + mlow + 8], ph1);
            atomicAdd(&pbuf[128 + mlow + 8], ph2);
        }
    }
    __syncthreads();
    if (tid < 192) {
        const int c = tid >> 6, m = tid & 63;
        float z = pbuf[c * 64 + m] + b3s[c];
        out[((long long)b * 3 + c) * HW + hw0 + m] = __fdividef(1.0f, 1.0f + __expf(-z));
    }
}

// ---------------- launch ----------------
extern "C" void kernel_launch(void* const* d_in, const int* in_sizes, int n_in,
                              void* d_out, int out_size) {
    const float* rgb  = (const float*)d_in[0];
    const int*   sidx = (const int*)d_in[1];
    const float* emb  = (const float*)d_in[2];
    const float* W0   = (const float*)d_in[3];
    const float* b0   = (const float*)d_in[4];
    const float* W1   = (const float*)d_in[5];
    const float* b1   = (const float*)d_in[6];
    const float* W2   = (const float*)d_in[7];
    const float* b2   = (const float*)d_in[8];
    const float* W3   = (const float*)d_in[9];
    const float* b3   = (const float*)d_in[10];
    float* out = (float*)d_out;

    const int B = in_sizes[1];
    const long long HW = (long long)in_sizes[0] / (3LL * B);
    const long long N  = (long long)B * HW;

    static bool attr_set = false;
    if (!attr_set) {
        cudaFuncSetAttribute(nilut_mma, cudaFuncAttributeMaxDynamicSharedMemorySize, SMEM_TOTAL);
        attr_set = true;
    }

    prep_kernel<<<512, HID>>>(emb, W0, b0, W1, W2);
    nilut_mma<<<(unsigned)(N / MT), THREADS, SMEM_TOTAL>>>(
        rgb, sidx, W0, b1, b2, W3, b3, out, (int)HW);
}

// round 12
// speedup vs baseline: 4.6526x; 1.2123x over previous
#include <cuda_runtime.h>
#include <cuda_fp16.h>
#include <math.h>
#include <stdint.h>

#define HID 256
#define NSTY 8
#define SDIM 64
#define MT 64
#define THREADS 256

// activation SMEM pitch: 264 fp16 = 528B (conflict-staggered ldmatrix rows)
#define APITCHB 528

// SMEM layout (bytes)
#define SO_ACT   0                // 64*528 = 33792 (single fp16 act)
#define SO_WBUF  33792            // 4 stages x 16KB (one k32 hi-chunk per stage)
#define SO_W0    99328            // 3*256 f32
#define SO_C0    102400           // 256 f32
#define SO_B1    103424           // 256 f32
#define SO_B2    104448           // 256 f32
#define SO_W3    105472           // 3*256 f32 (w3s[c*256+k])
#define SO_B3    108544           // 3 f32 (+pad)
#define SO_PBUF  108560           // 3*64 f32
#define SMEM_TOTAL 109328         // <= 113.5KB -> 2 CTAs/SM

// ---------------- device globals ----------------
__device__ float g_c0[NSTY][HID];
// [layer] x 65536 fp16 (256x256), laid out as [kc(16)][nb(32)][sub(2)][row(8)][col(8)]
__device__ __align__(16) __half g_Wh[2][65536];

// ---------------- helpers ----------------
__device__ __forceinline__ uint32_t smem_to_u32(const void* p) {
    uint32_t a;
    asm("{ .reg .u64 t; cvta.to.shared.u64 t, %1; cvt.u32.u64 %0, t; }" : "=r"(a) : "l"(p));
    return a;
}
#define LDSM4(R, addr) \
    asm volatile("ldmatrix.sync.aligned.m8n8.x4.shared.b16 {%0,%1,%2,%3}, [%4];" \
        : "=r"((R)[0]), "=r"((R)[1]), "=r"((R)[2]), "=r"((R)[3]) : "r"(addr))
#define MMA_F16(dd, a, b0_, b1_) \
    asm volatile("mma.sync.aligned.m16n8k16.row.col.f32.f16.f16.f32 " \
        "{%0,%1,%2,%3}, {%4,%5,%6,%7}, {%8,%9}, {%0,%1,%2,%3};" \
        : "+f"((dd)[0]), "+f"((dd)[1]), "+f"((dd)[2]), "+f"((dd)[3]) \
        : "r"((a)[0]), "r"((a)[1]), "r"((a)[2]), "r"((a)[3]), "r"(b0_), "r"(b1_))
#define CP_ASYNC16(dst, src) \
    asm volatile("cp.async.cg.shared.global [%0], [%1], 16;" :: "r"(dst), "l"(src) : "memory")
#define CP_COMMIT() asm volatile("cp.async.commit_group;" ::: "memory")
#define CP_WAIT2()  asm volatile("cp.async.wait_group 2;" ::: "memory")
#define CP_WAIT1()  asm volatile("cp.async.wait_group 1;" ::: "memory")
#define CP_WAIT0()  asm volatile("cp.async.wait_group 0;" ::: "memory")

__device__ __forceinline__ float gelu_f(float x) {
    // 0.5*x*(1+erf(x/sqrt(2))), erf via Abramowitz-Stegun 7.1.26 (|err|<=1.5e-7)
    float u  = x * 0.70710678118654752f;
    float au = fabsf(u);
    float t  = __fdividef(1.0f, fmaf(0.3275911f, au, 1.0f));
    float p  = t * fmaf(t, fmaf(t, fmaf(t, fmaf(t, 1.061405429f, -1.453152027f),
                                        1.421413741f), -0.284496736f), 0.254829592f);
    float er = 1.0f - p * __expf(-au * au);
    er = copysignf(er, u);
    return 0.5f * x * (1.0f + er);
}
__device__ __forceinline__ uint32_t pack2h(float a, float b) {
    __half2 t = __floats2half2_rn(a, b);
    return *reinterpret_cast<uint32_t*>(&t);
}

// ---------------- merged prologue kernel ----------------
__global__ void prep_kernel(const float* __restrict__ emb,
                            const float* __restrict__ W0,
                            const float* __restrict__ b0,
                            const float* __restrict__ W1,
                            const float* __restrict__ W2) {
    // fp16 weight quantize + fragment rearrange
    int l = blockIdx.x >> 8, n = blockIdx.x & 255, k = threadIdx.x;
    const float* Ws = l ? W2 : W1;
    float w = Ws[k * HID + n];
    int off = ((((k >> 4) * 32 + (n >> 3)) * 2 + ((k >> 3) & 1)) * 8 + (n & 7)) * 8 + (k & 7);
    g_Wh[l][off] = __float2half_rn(w);

    // folded per-style bias (blocks 0-7)
    if (blockIdx.x < NSTY) {
        int s = blockIdx.x, j = threadIdx.x;
        float a = b0[j];
        const float* e = emb + s * SDIM;
        #pragma unroll 8
        for (int d = 0; d < SDIM; d++) a += e[d] * W0[(3 + d) * HID + j];
        g_c0[s][j] = a;
    }
}

// ---------------- weight chunk streaming (k32 chunks, 16KB hi-only) ----------------
__device__ __forceinline__ void load_chunk(int it, uint32_t sb, int tid) {
    int l = it >> 3, kc2 = it & 7;
    uint32_t dbase = sb + SO_WBUF + (uint32_t)(it & 3) * 16384u;
    const char* srcbase = (const char*)&g_Wh[l][0] + kc2 * 16384;
    #pragma unroll
    for (int i = 0; i < 4; i++) {
        int idx = tid + i * 256;               // 0..1023 (16B units)
        CP_ASYNC16(dbase + (uint32_t)idx * 16u, srcbase + idx * 16);
    }
    CP_COMMIT();
}

// ---------------- main kernel ----------------
__global__ void __launch_bounds__(THREADS, 2)
nilut_mma(const float* __restrict__ rgb, const int* __restrict__ sidx,
          const float* __restrict__ W0,
          const float* __restrict__ b1, const float* __restrict__ b2,
          const float* __restrict__ W3, const float* __restrict__ b3,
          float* __restrict__ out, int HW)
{
    extern __shared__ __align__(128) char smem[];
    uint32_t sb = smem_to_u32(smem);
    float* w0s  = (float*)(smem + SO_W0);
    float* c0s  = (float*)(smem + SO_C0);
    float* b1s  = (float*)(smem + SO_B1);
    float* b2s  = (float*)(smem + SO_B2);
    float* w3s  = (float*)(smem + SO_W3);
    float* b3s  = (float*)(smem + SO_B3);
    float* pbuf = (float*)(smem + SO_PBUF);

    const int tid = threadIdx.x, wid = tid >> 5, lane = tid & 31;
    const int warp_m = wid >> 2, warp_n = wid & 3;   // 2 x 4 warp grid, 32x64 warp tile

    const long long base = (long long)blockIdx.x * MT;
    const int b = (int)(base / HW), hw0 = (int)(base % HW);
    const int style = sidx[b];

    // prefetch first three k32 chunks (layer-1, k0-95)
    load_chunk(0, sb, tid);
    load_chunk(1, sb, tid);
    load_chunk(2, sb, tid);

    // stage small tensors
    for (int i = tid; i < 768; i += THREADS) w0s[i] = W0[i];
    c0s[tid] = g_c0[style][tid];
    b1s[tid] = b1[tid];
    b2s[tid] = b2[tid];
    for (int i = tid; i < 768; i += THREADS) { int c = i >> 8, k = i & 255; w3s[i] = W3[k * 3 + c]; }
    if (tid < 3) b3s[tid] = b3[tid];
    if (tid < 192) pbuf[tid] = 0.f;
    __syncthreads();

    // ---- layer 0: SIMT, write act fp16 (4 threads per pixel, 64 n-cols each) ----
    {
        const int m = tid >> 2, q = tid & 3;
        const float r0 = rgb[((long long)b * 3 + 0) * HW + hw0 + m];
        const float r1 = rgb[((long long)b * 3 + 1) * HW + hw0 + m];
        const float r2 = rgb[((long long)b * 3 + 2) * HW + hw0 + m];
        uint32_t arow = (uint32_t)m * APITCHB + (uint32_t)q * 128u;  // byte offset (q*64 cols * 2B)
        #pragma unroll 4
        for (int i = 0; i < 32; i++) {
            int n = q * 64 + 2 * i;
            float z0 = c0s[n]     + r0 * w0s[n]     + r1 * w0s[256 + n]     + r2 * w0s[512 + n];
            float z1 = c0s[n + 1] + r0 * w0s[n + 1] + r1 * w0s[256 + n + 1] + r2 * w0s[512 + n + 1];
            *(uint32_t*)(smem + SO_ACT + arow + 4u * i) = pack2h(gelu_f(z0), gelu_f(z1));
        }
    }

    // per-lane ldmatrix offsets
    const uint32_t arow_l = (uint32_t)((lane & 7) + ((lane >> 3) & 1) * 8);
    const uint32_t akoff  = (uint32_t)(((lane >> 4) & 1) * 8);

    float d[2][8][4];
    #pragma unroll
    for (int mf = 0; mf < 2; mf++)
        #pragma unroll
        for (int nb = 0; nb < 8; nb++)
            #pragma unroll
            for (int e = 0; e < 4; e++) d[mf][nb][e] = 0.f;

    // ---- layers 1 & 2: 16 k32-iterations, 4-stage pipeline, 1 barrier/iteration ----
    #pragma unroll
    for (int it = 0; it < 16; it++) {
        if (it <= 13) { CP_WAIT2(); } else if (it == 14) { CP_WAIT1(); } else { CP_WAIT0(); }
        __syncthreads();      // chunk it visible; all warps done with stage (it+3)&3
        if (it <= 12) load_chunk(it + 3, sb, tid);

        uint32_t buf = sb + SO_WBUF + (uint32_t)(it & 3) * 16384u;
        // prefetch A fragments for both k16 sub-steps (independent of B LDSMs)
        uint32_t ah[2][2][4];
        #pragma unroll
        for (int kcs = 0; kcs < 2; kcs++) {
            uint32_t col = (uint32_t)(((it & 7) * 2 + kcs) * 16) + akoff;
            #pragma unroll
            for (int mf = 0; mf < 2; mf++) {
                uint32_t row = (uint32_t)(warp_m * 32 + mf * 16) + arow_l;
                LDSM4(ah[kcs][mf], sb + SO_ACT + row * APITCHB + col * 2u);
            }
        }
        #pragma unroll
        for (int kcs = 0; kcs < 2; kcs++) {
            #pragma unroll
            for (int nbp = 0; nbp < 4; nbp++) {
                uint32_t bd = buf + (uint32_t)kcs * 8192u
                            + (uint32_t)((warp_n * 8 + nbp * 2) * 256) + (uint32_t)lane * 16u;
                uint32_t bh[4];
                LDSM4(bh, bd);
                MMA_F16(d[0][nbp * 2 + 0], ah[kcs][0], bh[0], bh[1]);
                MMA_F16(d[1][nbp * 2 + 0], ah[kcs][1], bh[0], bh[1]);
                MMA_F16(d[0][nbp * 2 + 1], ah[kcs][0], bh[2], bh[3]);
                MMA_F16(d[1][nbp * 2 + 1], ah[kcs][1], bh[2], bh[3]);
            }
        }

        if (it == 7) {
            // ---- mid epilogue: bias + GELU, write act fp16 ----
            __syncthreads();   // all warps done reading layer-1 act before overwrite
            #pragma unroll
            for (int mf = 0; mf < 2; mf++) {
                #pragma unroll
                for (int nb = 0; nb < 8; nb++) {
                    int n0 = warp_n * 64 + nb * 8 + (lane & 3) * 2;
                    float bb0 = b1s[n0], bb1 = b1s[n0 + 1];
                    int mlow = warp_m * 32 + mf * 16 + (lane >> 2);
                    float g0 = gelu_f(d[mf][nb][0] + bb0);
                    float g1 = gelu_f(d[mf][nb][1] + bb1);
                    float g2 = gelu_f(d[mf][nb][2] + bb0);
                    float g3 = gelu_f(d[mf][nb][3] + bb1);
                    uint32_t offA = (uint32_t)mlow * APITCHB + (uint32_t)n0 * 2u;
                    *(uint32_t*)(smem + SO_ACT + offA) = pack2h(g0, g1);
                    *(uint32_t*)(smem + SO_ACT + offA + 8u * APITCHB) = pack2h(g2, g3);
                }
            }
            #pragma unroll
            for (int mf = 0; mf < 2; mf++)
                #pragma unroll
                for (int nb = 0; nb < 8; nb++)
                    #pragma unroll
                    for (int e = 0; e < 4; e++) d[mf][nb][e] = 0.f;
            // next iteration's leading __syncthreads orders these writes vs LDSM reads
        }
    }

    // ---- final epilogue: bias + GELU + layer3 dot + reduce ----
    #pragma unroll
    for (int mf = 0; mf < 2; mf++) {
        float pl0 = 0.f, pl1 = 0.f, pl2 = 0.f, ph0 = 0.f, ph1 = 0.f, ph2 = 0.f;
        #pragma unroll
        for (int nb = 0; nb < 8; nb++) {
            int n0 = warp_n * 64 + nb * 8 + (lane & 3) * 2;
            float bb0 = b2s[n0], bb1 = b2s[n0 + 1];
            float g0 = gelu_f(d[mf][nb][0] + bb0);
            float g1 = gelu_f(d[mf][nb][1] + bb1);
            float g2 = gelu_f(d[mf][nb][2] + bb0);
            float g3 = gelu_f(d[mf][nb][3] + bb1);
            float wa0 = w3s[n0], wa1 = w3s[n0 + 1];
            float wb0 = w3s[256 + n0], wb1 = w3s[256 + n0 + 1];
            float wc0 = w3s[512 + n0], wc1 = w3s[512 + n0 + 1];
            pl0 += g0 * wa0 + g1 * wa1;  ph0 += g2 * wa0 + g3 * wa1;
            pl1 += g0 * wb0 + g1 * wb1;  ph1 += g2 * wb0 + g3 * wb1;
            pl2 += g0 * wc0 + g1 * wc1;  ph2 += g2 * wc0 + g3 * wc1;
        }
        #pragma unroll
        for (int s = 1; s <= 2; s <<= 1) {
            pl0 += __shfl_xor_sync(0xFFFFFFFF, pl0, s);
            pl1 += __shfl_xor_sync(0xFFFFFFFF, pl1, s);
            pl2 += __shfl_xor_sync(0xFFFFFFFF, pl2, s);
            ph0 += __shfl_xor_sync(0xFFFFFFFF, ph0, s);
            ph1 += __shfl_xor_sync(0xFFFFFFFF, ph1, s);
            ph2 += __shfl_xor_sync(0xFFFFFFFF, ph2, s);
        }
        if ((lane & 3) == 0) {
            int mlow = warp_m * 32 + mf * 16 + (lane >> 2);
            atomicAdd(&pbuf[mlow], pl0);
            atomicAdd(&pbuf[64 + mlow], pl1);
            atomicAdd(&pbuf[128 + mlow], pl2);
            atomicAdd(&pbuf[mlow + 8], ph0);
            atomicAdd(&pbuf[64 + mlow + 8], ph1);
            atomicAdd(&pbuf[128 + mlow + 8], ph2);
        }
    }
    __syncthreads();
    if (tid < 192) {
        const int c = tid >> 6, m = tid & 63;
        float z = pbuf[c * 64 + m] + b3s[c];
        out[((long long)b * 3 + c) * HW + hw0 + m] = __fdividef(1.0f, 1.0f + __expf(-z));
    }
}

// ---------------- launch ----------------
extern "C" void kernel_launch(void* const* d_in, const int* in_sizes, int n_in,
                              void* d_out, int out_size) {
    const float* rgb  = (const float*)d_in[0];
    const int*   sidx = (const int*)d_in[1];
    const float* emb  = (const float*)d_in[2];
    const float* W0   = (const float*)d_in[3];
    const float* b0   = (const float*)d_in[4];
    const float* W1   = (const float*)d_in[5];
    const float* b1   = (const float*)d_in[6];
    const float* W2   = (const float*)d_in[7];
    const float* b2   = (const float*)d_in[8];
    const float* W3   = (const float*)d_in[9];
    const float* b3   = (const float*)d_in[10];
    float* out = (float*)d_out;

    const int B = in_sizes[1];
    const long long HW = (long long)in_sizes[0] / (3LL * B);
    const long long N  = (long long)B * HW;

    static bool attr_set = false;
    if (!attr_set) {
        cudaFuncSetAttribute(nilut_mma, cudaFuncAttributeMaxDynamicSharedMemorySize, SMEM_TOTAL);
        attr_set = true;
    }

    prep_kernel<<<512, HID>>>(emb, W0, b0, W1, W2);
    nilut_mma<<<(unsigned)(N / MT), THREADS, SMEM_TOTAL>>>(
        rgb, sidx, W0, b1, b2, W3, b3, out, (int)HW);
}